// round 15
// baseline (speedup 1.0000x reference)
#include <cuda_runtime.h>

// Problem constants (fixed shapes from reference)
#define BB 8
#define LL 6656
#define DD 1024
#define WW 13
#define CC 512          // LL / WW
#define D4 256          // DD / 4
#define ROLL 5

__device__ __forceinline__ float4 f4min(float4 a, float4 b) {
    return make_float4(fminf(a.x, b.x), fminf(a.y, b.y), fminf(a.z, b.z), fminf(a.w, b.w));
}
__device__ __forceinline__ float4 f4max(float4 a, float4 b) {
    return make_float4(fmaxf(a.x, b.x), fmaxf(a.y, b.y), fmaxf(a.z, b.z), fmaxf(a.w, b.w));
}

__global__ __launch_bounds__(256, 3)
void window_sort_kernel(const float4* __restrict__ v, float4* __restrict__ out) {
    const int tid = blockIdx.x * blockDim.x + threadIdx.x;
    // tid layout: [b (3b)][c (9b)][d4 (8b)]  -> total 2^20 threads
    const int d4 = tid & (D4 - 1);
    const int c  = (tid >> 8) & (CC - 1);
    const int b  = tid >> 17;

    const long base = (long)b * (LL * (long)D4) + d4;

    // Row indices: p_w = (w*512 + c + 5) mod 6656. Only w=12 with c>=507 wraps.
    // 13 independent pre-reduced offsets: the load batch issues with no shared
    // dependency chain beyond `base`.
    int pos[WW];
#pragma unroll
    for (int w = 0; w < WW; w++) {
        int p = w * CC + c + ROLL;
        if (p >= LL) p -= LL;
        pos[w] = p;
    }

    // All 13 streaming loads issued back-to-back: MLP=13 per thread,
    // each row a perfectly coalesced 512B warp-burst.
    float4 a[WW];
#pragma unroll
    for (int w = 0; w < WW; w++) {
        a[w] = __ldcs(v + base + (long)pos[w] * D4);
    }

    // Optimal 13-input sorting network: 45 compare-exchanges, depth 10.
#define CE(i, j) { float4 lo = f4min(a[i], a[j]); float4 hi = f4max(a[i], a[j]); a[i] = lo; a[j] = hi; }
    // layer 1
    CE(0,12) CE(1,10) CE(2,9) CE(3,7) CE(5,11) CE(6,8)
    // layer 2
    CE(1,6) CE(2,3) CE(4,11) CE(7,9) CE(8,10)
    // layer 3
    CE(0,4) CE(1,2) CE(3,6) CE(7,8) CE(9,10) CE(11,12)
    // layer 4
    CE(4,6) CE(5,9) CE(8,11) CE(10,12)
    // layer 5
    CE(0,5) CE(3,8) CE(4,7) CE(6,11) CE(9,10)
    // layer 6
    CE(0,1) CE(2,5) CE(6,9) CE(7,8) CE(10,11)
    // layer 7
    CE(1,3) CE(2,4) CE(5,6) CE(9,10)
    // layer 8
    CE(1,2) CE(3,4) CE(5,7) CE(6,8)
    // layer 9
    CE(2,3) CE(4,5) CE(6,7) CE(8,9)
    // layer 10
    CE(3,4) CE(5,6)
#undef CE

    // Streaming stores back to the same 13 rows (write-once, never re-read).
#pragma unroll
    for (int w = 0; w < WW; w++) {
        __stcs(out + base + (long)pos[w] * D4, a[w]);
    }
}

extern "C" void kernel_launch(void* const* d_in, const int* in_sizes, int n_in,
                              void* d_out, int out_size) {
    // inputs: q (d_in[0]), k (d_in[1]), v (d_in[2]); only v is used.
    const float4* v = (const float4*)d_in[2];
    float4* out = (float4*)d_out;

    const int total_threads = BB * CC * D4;  // 1,048,576
    const int block = 256;
    const int grid = total_threads / block;  // 4096
    window_sort_kernel<<<grid, block>>>(v, out);
}

// round 16
// speedup vs baseline: 1.0038x; 1.0038x over previous
#include <cuda_runtime.h>

// Problem constants (fixed shapes from reference)
#define BB 8
#define LL 6656
#define DD 1024
#define WW 13
#define CC 512          // LL / WW
#define D4 256          // DD / 4
#define ROLL 5

__device__ __forceinline__ float4 f4min(float4 a, float4 b) {
    return make_float4(fminf(a.x, b.x), fminf(a.y, b.y), fminf(a.z, b.z), fminf(a.w, b.w));
}
__device__ __forceinline__ float4 f4max(float4 a, float4 b) {
    return make_float4(fmaxf(a.x, b.x), fmaxf(a.y, b.y), fmaxf(a.z, b.z), fmaxf(a.w, b.w));
}

__global__ __launch_bounds__(512, 2)
void window_sort_kernel(const float4* __restrict__ v, float4* __restrict__ out) {
    const int tid = blockIdx.x * blockDim.x + threadIdx.x;
    // tid layout: [b (3b)][c (9b)][d4 (8b)]  -> total 2^20 threads
    const int d4 = tid & (D4 - 1);
    const int c  = (tid >> 8) & (CC - 1);
    const int b  = tid >> 17;

    const long base = (long)b * (LL * (long)D4) + d4;

    // Row indices: p_w = (w*512 + c + 5) mod 6656. Only w=12 with c>=507 wraps.
    // 13 independent pre-reduced offsets: the load batch issues with no shared
    // dependency chain beyond `base`.
    int pos[WW];
#pragma unroll
    for (int w = 0; w < WW; w++) {
        int p = w * CC + c + ROLL;
        if (p >= LL) p -= LL;
        pos[w] = p;
    }

    // All 13 streaming loads issued back-to-back: MLP=13 per thread,
    // each row a perfectly coalesced 512B warp-burst.
    float4 a[WW];
#pragma unroll
    for (int w = 0; w < WW; w++) {
        a[w] = __ldcs(v + base + (long)pos[w] * D4);
    }

    // Optimal 13-input sorting network: 45 compare-exchanges, depth 10.
#define CE(i, j) { float4 lo = f4min(a[i], a[j]); float4 hi = f4max(a[i], a[j]); a[i] = lo; a[j] = hi; }
    // layer 1
    CE(0,12) CE(1,10) CE(2,9) CE(3,7) CE(5,11) CE(6,8)
    // layer 2
    CE(1,6) CE(2,3) CE(4,11) CE(7,9) CE(8,10)
    // layer 3
    CE(0,4) CE(1,2) CE(3,6) CE(7,8) CE(9,10) CE(11,12)
    // layer 4
    CE(4,6) CE(5,9) CE(8,11) CE(10,12)
    // layer 5
    CE(0,5) CE(3,8) CE(4,7) CE(6,11) CE(9,10)
    // layer 6
    CE(0,1) CE(2,5) CE(6,9) CE(7,8) CE(10,11)
    // layer 7
    CE(1,3) CE(2,4) CE(5,6) CE(9,10)
    // layer 8
    CE(1,2) CE(3,4) CE(5,7) CE(6,8)
    // layer 9
    CE(2,3) CE(4,5) CE(6,7) CE(8,9)
    // layer 10
    CE(3,4) CE(5,6)
#undef CE

    // Streaming stores back to the same 13 rows (write-once, never re-read).
#pragma unroll
    for (int w = 0; w < WW; w++) {
        __stcs(out + base + (long)pos[w] * D4, a[w]);
    }
}

extern "C" void kernel_launch(void* const* d_in, const int* in_sizes, int n_in,
                              void* d_out, int out_size) {
    // inputs: q (d_in[0]), k (d_in[1]), v (d_in[2]); only v is used.
    const float4* v = (const float4*)d_in[2];
    float4* out = (float4*)d_out;

    const int total_threads = BB * CC * D4;  // 1,048,576
    const int block = 512;
    const int grid = total_threads / block;  // 2048
    window_sort_kernel<<<grid, block>>>(v, out);
}

// round 17
// speedup vs baseline: 1.0095x; 1.0057x over previous
#include <cuda_runtime.h>

// Problem constants (fixed shapes from reference)
#define BB 8
#define LL 6656
#define DD 1024
#define WW 13
#define CC 512          // LL / WW
#define D4 256          // DD / 4
#define ROLL 5

__device__ __forceinline__ float4 f4min(float4 a, float4 b) {
    return make_float4(fminf(a.x, b.x), fminf(a.y, b.y), fminf(a.z, b.z), fminf(a.w, b.w));
}
__device__ __forceinline__ float4 f4max(float4 a, float4 b) {
    return make_float4(fmaxf(a.x, b.x), fmaxf(a.y, b.y), fmaxf(a.z, b.z), fmaxf(a.w, b.w));
}

__global__ __launch_bounds__(256, 3)
void window_sort_kernel(const float4* __restrict__ v, float4* __restrict__ out) {
    const int tid = blockIdx.x * blockDim.x + threadIdx.x;
    // tid layout: [b (3b)][c (9b)][d4 (8b)]  -> total 2^20 threads
    const int d4 = tid & (D4 - 1);
    const int c  = (tid >> 8) & (CC - 1);
    const int b  = tid >> 17;

    const long base = (long)b * (LL * (long)D4) + d4;

    // Row indices: p_w = (w*512 + c + 5) mod 6656. Only w=12 with c>=507 wraps.
    // 13 independent pre-reduced offsets: the load batch issues with no shared
    // dependency chain beyond `base`.
    int pos[WW];
#pragma unroll
    for (int w = 0; w < WW; w++) {
        int p = w * CC + c + ROLL;
        if (p >= LL) p -= LL;
        pos[w] = p;
    }

    // All 13 streaming loads issued back-to-back: MLP=13 per thread,
    // each row a perfectly coalesced 512B warp-burst.
    float4 a[WW];
#pragma unroll
    for (int w = 0; w < WW; w++) {
        a[w] = __ldcs(v + base + (long)pos[w] * D4);
    }

    // Optimal 13-input sorting network: 45 compare-exchanges, depth 10.
#define CE(i, j) { float4 lo = f4min(a[i], a[j]); float4 hi = f4max(a[i], a[j]); a[i] = lo; a[j] = hi; }
    // layer 1
    CE(0,12) CE(1,10) CE(2,9) CE(3,7) CE(5,11) CE(6,8)
    // layer 2
    CE(1,6) CE(2,3) CE(4,11) CE(7,9) CE(8,10)
    // layer 3
    CE(0,4) CE(1,2) CE(3,6) CE(7,8) CE(9,10) CE(11,12)
    // layer 4
    CE(4,6) CE(5,9) CE(8,11) CE(10,12)
    // layer 5
    CE(0,5) CE(3,8) CE(4,7) CE(6,11) CE(9,10)
    // layer 6
    CE(0,1) CE(2,5) CE(6,9) CE(7,8) CE(10,11)
    // layer 7
    CE(1,3) CE(2,4) CE(5,6) CE(9,10)
    // layer 8
    CE(1,2) CE(3,4) CE(5,7) CE(6,8)
    // layer 9
    CE(2,3) CE(4,5) CE(6,7) CE(8,9)
    // layer 10
    CE(3,4) CE(5,6)
#undef CE

    // Streaming stores back to the same 13 rows (write-once, never re-read).
#pragma unroll
    for (int w = 0; w < WW; w++) {
        __stcs(out + base + (long)pos[w] * D4, a[w]);
    }
}

extern "C" void kernel_launch(void* const* d_in, const int* in_sizes, int n_in,
                              void* d_out, int out_size) {
    // inputs: q (d_in[0]), k (d_in[1]), v (d_in[2]); only v is used.
    const float4* v = (const float4*)d_in[2];
    float4* out = (float4*)d_out;

    const int total_threads = BB * CC * D4;  // 1,048,576
    const int block = 256;
    const int grid = total_threads / block;  // 4096
    window_sort_kernel<<<grid, block>>>(v, out);
}